// round 14
// baseline (speedup 1.0000x reference)
#include <cuda_runtime.h>
#include <cuda_bf16.h>
#include <cstdint>

typedef unsigned long long ull;

#define BSZ   256
#define LSEQ  2048
#define DD    128   // DIN == DOUT == 128

// ---------------------------------------------------------------------------
// Scratch: projections (fp32) + pre-split bf16 weights (hi/lo).
// ---------------------------------------------------------------------------
__device__ float d_U [BSZ * LSEQ * DD];
__device__ float d_Gx[BSZ * LSEQ * DD];
__device__ float d_Ax[BSZ * LSEQ * DD];
__device__ __nv_bfloat16 d_Wh[3 * DD * DD];   // [m][o][d] K-major
__device__ __nv_bfloat16 d_Wl[3 * DD * DD];

// ---------------------------------------------------------------------------
// small helpers
// ---------------------------------------------------------------------------
__device__ __forceinline__ ull ffma2(ull a, ull b, ull c) {
    ull d;
    asm("fma.rn.f32x2 %0, %1, %2, %3;" : "=l"(d) : "l"(a), "l"(b), "l"(c));
    return d;
}
__device__ __forceinline__ ull fadd2(ull a, ull b) {
    ull d;
    asm("add.rn.f32x2 %0, %1, %2;" : "=l"(d) : "l"(a), "l"(b));
    return d;
}
__device__ __forceinline__ float2 upk2(ull v) {
    float2 f;
    asm("mov.b64 {%0, %1}, %2;" : "=f"(f.x), "=f"(f.y) : "l"(v));
    return f;
}
__device__ __forceinline__ float tanh_hw(float x) {
    float r;
    asm("tanh.approx.f32 %0, %1;" : "=f"(r) : "f"(x));
    return r;
}
__device__ __forceinline__ float tanhf_fast(float x) {
    float ax = fabsf(x);
    float e  = __expf(-2.0f * ax);
    float r  = __fdividef(1.0f - e, 1.0f + e);
    return copysignf(r, x);
}
__device__ __forceinline__ uint32_t pack_bf2(float a, float b) {
    __nv_bfloat162 t = __floats2bfloat162_rn(a, b);
    return *(uint32_t*)&t;
}

// mma.sync m16n8k16 row.col f32.bf16.bf16.f32 (baseline PTX, legal at compute_103)
__device__ __forceinline__ void mma16816(float* c, const uint32_t* a, const uint32_t* b) {
    asm volatile(
        "mma.sync.aligned.m16n8k16.row.col.f32.bf16.bf16.f32 "
        "{%0,%1,%2,%3}, {%4,%5,%6,%7}, {%8,%9}, {%0,%1,%2,%3};"
        : "+f"(c[0]), "+f"(c[1]), "+f"(c[2]), "+f"(c[3])
        : "r"(a[0]), "r"(a[1]), "r"(a[2]), "r"(a[3]), "r"(b[0]), "r"(b[1]));
}

// ldmatrix x4 (baseline PTX sm_75+)
__device__ __forceinline__ void ldm_x4(uint32_t* r, uint32_t saddr) {
    asm volatile("ldmatrix.sync.aligned.m8n8.x4.shared.b16 {%0,%1,%2,%3}, [%4];"
                 : "=r"(r[0]), "=r"(r[1]), "=r"(r[2]), "=r"(r[3]) : "r"(saddr));
}

// ---------------------------------------------------------------------------
// Prep kernel: split weights into bf16 hi/lo (once, tiny).
// ---------------------------------------------------------------------------
__global__ void rwa_prep_kernel(const float* __restrict__ u_w,
                                const float* __restrict__ g_w,
                                const float* __restrict__ a_w)
{
    int idx = blockIdx.x * blockDim.x + threadIdx.x;
    if (idx >= 3 * DD * DD) return;
    int m = idx / (DD * DD);
    int r = idx - m * DD * DD;
    int o = r >> 7, d = r & 127;
    float w = (m == 0) ? u_w[o * 128 + d]
            : (m == 1) ? g_w[o * 256 + d]
                       : a_w[o * 256 + d];
    __nv_bfloat16 h = __float2bfloat16_rn(w);
    float res = w - __bfloat162float(h);
    d_Wh[idx] = h;
    d_Wl[idx] = __float2bfloat16_rn(res);
}

// ---------------------------------------------------------------------------
// Projection GEMM on tensor cores (unchanged from best passing round):
// 3xBF16 split, 8 warps = 4(M) x 2(N), ldmatrix fragments.
// ---------------------------------------------------------------------------
#define PJ_STRIDE 68                       // b32 words per smem row
#define PJ_ROWB   (PJ_STRIDE * 4)          // 272 bytes
#define OFF_AH 0
#define OFF_AL (OFF_AH + 128 * PJ_ROWB)
#define OFF_WH (OFF_AL + 128 * PJ_ROWB)
#define OFF_WL (OFF_WH + 128 * PJ_ROWB)
#define OFF_BIAS (OFF_WL + 128 * PJ_ROWB)
#define PJ_SMEM (OFF_BIAS + 1024)

__global__ void __launch_bounds__(256, 1)
rwa_proj_mma_kernel(const float* __restrict__ x,
                    const float* __restrict__ u_b,
                    const float* __restrict__ g_b)
{
    extern __shared__ char smem[];
    uint32_t* Ah = (uint32_t*)(smem + OFF_AH);
    uint32_t* Al = (uint32_t*)(smem + OFF_AL);
    uint32_t* Wh = (uint32_t*)(smem + OFF_WH);
    uint32_t* Wl = (uint32_t*)(smem + OFF_WL);
    float* bias_s = (float*)(smem + OFF_BIAS);

    const int tid = threadIdx.x;
    const int wid = tid >> 5;
    const int lid = tid & 31;
    const int g   = lid >> 2;
    const int tig = lid & 3;
    const int wm  = wid & 3;
    const int wn  = wid >> 2;
    const int row0 = blockIdx.x * 128;

    const uint32_t sAh = (uint32_t)__cvta_generic_to_shared(Ah);
    const uint32_t sAl = (uint32_t)__cvta_generic_to_shared(Al);
    const uint32_t sWh = (uint32_t)__cvta_generic_to_shared(Wh);
    const uint32_t sWl = (uint32_t)__cvta_generic_to_shared(Wl);

    const uint32_t aoff = (uint32_t)((lid & 15) * PJ_ROWB + (lid >> 4) * 16);
    const uint32_t boff = (uint32_t)(((lid & 7) + ((lid >> 4) & 1) * 8) * PJ_ROWB
                                     + ((lid >> 3) & 1) * 16);

    if (tid < 128) {
        bias_s[tid]       = u_b[tid];
        bias_s[128 + tid] = g_b[tid];
    }

    {
        const float4* xp = (const float4*)(x + (size_t)row0 * DD);
        #pragma unroll
        for (int i = 0; i < 16; i++) {
            int f   = tid + i * 256;
            int row = f >> 5;
            int c4  = f & 31;
            float4 v = xp[f];
            __nv_bfloat16 h0 = __float2bfloat16_rn(v.x);
            __nv_bfloat16 h1 = __float2bfloat16_rn(v.y);
            __nv_bfloat16 h2 = __float2bfloat16_rn(v.z);
            __nv_bfloat16 h3 = __float2bfloat16_rn(v.w);
            int idx = row * PJ_STRIDE + c4 * 2;
            Ah[idx]     = pack_bf2(__bfloat162float(h0), __bfloat162float(h1));
            Ah[idx + 1] = pack_bf2(__bfloat162float(h2), __bfloat162float(h3));
            Al[idx]     = pack_bf2(v.x - __bfloat162float(h0),
                                   v.y - __bfloat162float(h1));
            Al[idx + 1] = pack_bf2(v.z - __bfloat162float(h2),
                                   v.w - __bfloat162float(h3));
        }
    }
    __syncthreads();

    for (int m = 0; m < 3; m++) {
        {
            const uint4* wh = (const uint4*)(d_Wh + m * DD * DD);
            const uint4* wl = (const uint4*)(d_Wl + m * DD * DD);
            #pragma unroll
            for (int i = 0; i < 8; i++) {
                int f  = tid + i * 256;
                int n  = f >> 4;
                int j4 = f & 15;
                int idx = n * PJ_STRIDE + j4 * 4;
                *(uint4*)(Wh + idx) = wh[f];
                *(uint4*)(Wl + idx) = wl[f];
            }
        }
        __syncthreads();

        float acc[2][8][4];
        #pragma unroll
        for (int i = 0; i < 2; i++)
            #pragma unroll
            for (int j = 0; j < 8; j++)
                #pragma unroll
                for (int c = 0; c < 4; c++) acc[i][j][c] = 0.0f;

        #pragma unroll
        for (int pass = 0; pass < 3; pass++) {
            const uint32_t sA = (pass == 2) ? sAl : sAh;
            const uint32_t sB = (pass == 1) ? sWl : sWh;
            #pragma unroll
            for (int ks = 0; ks < 8; ks++) {
                uint32_t a[2][4];
                #pragma unroll
                for (int i = 0; i < 2; i++) {
                    uint32_t addr = sA + (uint32_t)((wm * 32 + i * 16) * PJ_ROWB
                                                    + ks * 32) + aoff;
                    ldm_x4(a[i], addr);
                }
                uint32_t b[8][2];
                #pragma unroll
                for (int jp = 0; jp < 4; jp++) {
                    uint32_t r[4];
                    uint32_t addr = sB + (uint32_t)((wn * 64 + jp * 16) * PJ_ROWB
                                                    + ks * 32) + boff;
                    ldm_x4(r, addr);
                    b[2 * jp][0]     = r[0];
                    b[2 * jp][1]     = r[1];
                    b[2 * jp + 1][0] = r[2];
                    b[2 * jp + 1][1] = r[3];
                }
                #pragma unroll
                for (int i = 0; i < 2; i++)
                    #pragma unroll
                    for (int j = 0; j < 8; j++)
                        mma16816(acc[i][j], a[i], b[j]);
            }
        }

        float* dst = (m == 0) ? d_U : (m == 1) ? d_Gx : d_Ax;
        #pragma unroll
        for (int i = 0; i < 2; i++) {
            #pragma unroll
            for (int j = 0; j < 8; j++) {
                int r = row0 + wm * 32 + i * 16 + g;
                int c = wn * 64 + j * 8 + tig * 2;
                float bx = 0.0f, by = 0.0f;
                if (m < 2) {
                    bx = bias_s[m * 128 + c];
                    by = bias_s[m * 128 + c + 1];
                }
                float2 v0 = make_float2(acc[i][j][0] + bx, acc[i][j][1] + by);
                float2 v1 = make_float2(acc[i][j][2] + bx, acc[i][j][3] + by);
                *(float2*)(dst + (size_t)r * DD + c)       = v0;
                *(float2*)(dst + (size_t)(r + 8) * DD + c) = v1;
            }
        }
        __syncthreads();
    }
}

// ---------------------------------------------------------------------------
// Recurrent kernel v5: 256 CTAs (one batch each) x 128 threads (one per o).
// Each thread computes the FULL K=128 dot products for its channel:
//   - g_wh[o][:], a_wh[o][:] in registers (64+64 ull = 128 regs)
//   - h broadcast from smem (32 x LDS.128, all lanes same address)
//   - NO shuffles, NO reduction, NO redundant epilogues, 4-warp barrier only
// ~170 regs -> 2 CTAs/SM co-resident; independent CTAs hide each other's
// latency without any shared synchronization (fixes R5's 16-warp skew).
// Prefetch distance 2 (step time shrinks below DRAM latency).
// ---------------------------------------------------------------------------
__global__ void __launch_bounds__(128, 2)
rwa_rec_kernel(const float* __restrict__ g_w,
               const float* __restrict__ a_w,
               const float* __restrict__ s0,
               float* __restrict__ out)
{
    __shared__ __align__(16) float hs[2][DD];

    const int o = threadIdx.x;
    const int b = blockIdx.x;

    // full h-recurrence weight rows (cols 128..255), in registers
    ull wg[64], wa[64];
    {
        const ull* gp = (const ull*)(g_w + (size_t)o * 256 + 128);
        const ull* ap = (const ull*)(a_w + (size_t)o * 256 + 128);
        #pragma unroll
        for (int j = 0; j < 64; j++) { wg[j] = gp[j]; wa[j] = ap[j]; }
    }

    float num = 0.0f, den = 0.0f, amax = 1e-38f;
    const size_t idx0 = (size_t)b * LSEQ * DD + o;

    hs[0][o] = tanhf_fast(s0[o]);

    // prefetch pipeline: c = step t, n = step t+1
    float cu = d_U[idx0], cg = d_Gx[idx0], ca = d_Ax[idx0];
    float nu = d_U[idx0 + DD], ng = d_Gx[idx0 + DD], na = d_Ax[idx0 + DD];
    __syncthreads();

    for (int t = 0; t < LSEQ; t++) {
        // issue prefetch for t+2 (two steps of slack)
        float pu = 0.0f, pg = 0.0f, pa = 0.0f;
        if (t + 2 < LSEQ) {
            size_t id = idx0 + (size_t)(t + 2) * DD;
            pu = d_U[id]; pg = d_Gx[id]; pa = d_Ax[id];
        }

        // ---- full-K dot products (this thread's channel, this CTA's batch) ----
        const ulonglong2* hp = (const ulonglong2*)&hs[t & 1][0];
        ull aG0 = 0ull, aG1 = 0ull, aG2 = 0ull, aG3 = 0ull;
        ull aA0 = 0ull, aA1 = 0ull, aA2 = 0ull, aA3 = 0ull;
        #pragma unroll
        for (int j = 0; j < 16; j++) {
            ulonglong2 h01 = hp[2 * j];
            ulonglong2 h23 = hp[2 * j + 1];
            aG0 = ffma2(wg[4*j  ], h01.x, aG0);
            aA0 = ffma2(wa[4*j  ], h01.x, aA0);
            aG1 = ffma2(wg[4*j+1], h01.y, aG1);
            aA1 = ffma2(wa[4*j+1], h01.y, aA1);
            aG2 = ffma2(wg[4*j+2], h23.x, aG2);
            aA2 = ffma2(wa[4*j+2], h23.x, aA2);
            aG3 = ffma2(wg[4*j+3], h23.y, aG3);
            aA3 = ffma2(wa[4*j+3], h23.y, aA3);
        }
        ull gT = fadd2(fadd2(aG0, aG1), fadd2(aG2, aG3));
        ull aT = fadd2(fadd2(aA0, aA1), fadd2(aA2, aA3));
        float2 gv = upk2(gT);
        float2 av = upk2(aT);
        float sG = gv.x + gv.y;
        float sA = av.x + av.y;

        // ---- epilogue (one per thread, zero redundancy) ----
        float g  = tanh_hw(cg + sG);
        float z  = cu * g;
        float a  = ca + sA;
        float m  = fmaxf(a, amax);
        float e  = __expf(m - amax);
        amax = m;
        num  = fmaf(z, e, num);
        den += e;
        float h = tanh_hw(__fdividef(num, den));

        hs[(t + 1) & 1][o] = h;
        out[idx0 + (size_t)t * DD] = h;

        cu = nu; cg = ng; ca = na;
        nu = pu; ng = pg; na = pa;
        __syncthreads();   // publish h(t) for step t+1 (4 warps only)
    }
}

// ---------------------------------------------------------------------------
// kernel_launch
// Input order (metadata): 0:x  1:s0  2:u_w  3:u_b  4:g_w  5:g_b  6:a_w
// ---------------------------------------------------------------------------
extern "C" void kernel_launch(void* const* d_in, const int* in_sizes, int n_in,
                              void* d_out, int out_size)
{
    const float* x   = (const float*)d_in[0];
    const float* s0  = (const float*)d_in[1];
    const float* u_w = (const float*)d_in[2];
    const float* u_b = (const float*)d_in[3];
    const float* g_w = (const float*)d_in[4];
    const float* g_b = (const float*)d_in[5];
    const float* a_w = (const float*)d_in[6];
    float* out = (float*)d_out;

    // 1) split weights to bf16 hi/lo
    rwa_prep_kernel<<<(3 * DD * DD + 255) / 256, 256>>>(u_w, g_w, a_w);

    // 2) projections on tensor cores (mma.sync bf16, ldmatrix fragments)
    cudaFuncSetAttribute(rwa_proj_mma_kernel,
                         cudaFuncAttributeMaxDynamicSharedMemorySize, PJ_SMEM);
    rwa_proj_mma_kernel<<<(BSZ * LSEQ) / 128, 256, PJ_SMEM>>>(x, u_b, g_b);

    // 3) recurrence: one CTA per batch, one thread per channel
    rwa_rec_kernel<<<BSZ, 128>>>(g_w, a_w, s0, out);
}

// round 16
// speedup vs baseline: 1.8614x; 1.8614x over previous
#include <cuda_runtime.h>
#include <cuda_bf16.h>
#include <cstdint>

typedef unsigned long long ull;

#define BSZ   256
#define LSEQ  2048
#define DD    128   // DIN == DOUT == 128

// ---------------------------------------------------------------------------
// Scratch: projections (fp32) + pre-split bf16 weights (hi/lo).
// ---------------------------------------------------------------------------
__device__ float d_U [BSZ * LSEQ * DD];
__device__ float d_Gx[BSZ * LSEQ * DD];
__device__ float d_Ax[BSZ * LSEQ * DD];
__device__ __nv_bfloat16 d_Wh[3 * DD * DD];   // [m][o][d] K-major
__device__ __nv_bfloat16 d_Wl[3 * DD * DD];

// ---------------------------------------------------------------------------
// small helpers
// ---------------------------------------------------------------------------
__device__ __forceinline__ ull ffma2(ull a, ull b, ull c) {
    ull d;
    asm("fma.rn.f32x2 %0, %1, %2, %3;" : "=l"(d) : "l"(a), "l"(b), "l"(c));
    return d;
}
__device__ __forceinline__ float2 upk2(ull v) {
    float2 f;
    asm("mov.b64 {%0, %1}, %2;" : "=f"(f.x), "=f"(f.y) : "l"(v));
    return f;
}
__device__ __forceinline__ float tanh_hw(float x) {
    float r;
    asm("tanh.approx.f32 %0, %1;" : "=f"(r) : "f"(x));
    return r;
}
__device__ __forceinline__ float tanhf_fast(float x) {
    float ax = fabsf(x);
    float e  = __expf(-2.0f * ax);
    float r  = __fdividef(1.0f - e, 1.0f + e);
    return copysignf(r, x);
}
__device__ __forceinline__ uint32_t pack_bf2(float a, float b) {
    __nv_bfloat162 t = __floats2bfloat162_rn(a, b);
    return *(uint32_t*)&t;
}

// mma.sync m16n8k16 row.col f32.bf16.bf16.f32 (baseline PTX, legal at compute_103)
__device__ __forceinline__ void mma16816(float* c, const uint32_t* a, const uint32_t* b) {
    asm volatile(
        "mma.sync.aligned.m16n8k16.row.col.f32.bf16.bf16.f32 "
        "{%0,%1,%2,%3}, {%4,%5,%6,%7}, {%8,%9}, {%0,%1,%2,%3};"
        : "+f"(c[0]), "+f"(c[1]), "+f"(c[2]), "+f"(c[3])
        : "r"(a[0]), "r"(a[1]), "r"(a[2]), "r"(a[3]), "r"(b[0]), "r"(b[1]));
}

// ldmatrix x4 (baseline PTX sm_75+)
__device__ __forceinline__ void ldm_x4(uint32_t* r, uint32_t saddr) {
    asm volatile("ldmatrix.sync.aligned.m8n8.x4.shared.b16 {%0,%1,%2,%3}, [%4];"
                 : "=r"(r[0]), "=r"(r[1]), "=r"(r[2]), "=r"(r[3]) : "r"(saddr));
}

// ---------------------------------------------------------------------------
// Prep kernel: split weights into bf16 hi/lo (once, tiny).
// ---------------------------------------------------------------------------
__global__ void rwa_prep_kernel(const float* __restrict__ u_w,
                                const float* __restrict__ g_w,
                                const float* __restrict__ a_w)
{
    int idx = blockIdx.x * blockDim.x + threadIdx.x;
    if (idx >= 3 * DD * DD) return;
    int m = idx / (DD * DD);
    int r = idx - m * DD * DD;
    int o = r >> 7, d = r & 127;
    float w = (m == 0) ? u_w[o * 128 + d]
            : (m == 1) ? g_w[o * 256 + d]
                       : a_w[o * 256 + d];
    __nv_bfloat16 h = __float2bfloat16_rn(w);
    float res = w - __bfloat162float(h);
    d_Wh[idx] = h;
    d_Wl[idx] = __float2bfloat16_rn(res);
}

// ---------------------------------------------------------------------------
// Projection GEMM on tensor cores, 3xBF16 split (Ahi*Bhi + Ahi*Blo + Alo*Bhi).
// v2: 512 threads / 16 warps = 4(M) x 4(N); warp tile 32x32.
// Doubles warps per SMSP (2 -> 4) to raise HMMA issue density — the
// discriminating experiment for the legacy-HMMA pipe rate (512 vs 1024
// MAC/cyc/SM). Fragment math identical to the proven 8-warp version.
// ---------------------------------------------------------------------------
#define PJ_STRIDE 68                       // b32 words per smem row
#define PJ_ROWB   (PJ_STRIDE * 4)          // 272 bytes
#define OFF_AH 0
#define OFF_AL (OFF_AH + 128 * PJ_ROWB)
#define OFF_WH (OFF_AL + 128 * PJ_ROWB)
#define OFF_WL (OFF_WH + 128 * PJ_ROWB)
#define OFF_BIAS (OFF_WL + 128 * PJ_ROWB)
#define PJ_SMEM (OFF_BIAS + 1024)

__global__ void __launch_bounds__(512, 1)
rwa_proj_mma_kernel(const float* __restrict__ x,
                    const float* __restrict__ u_b,
                    const float* __restrict__ g_b)
{
    extern __shared__ char smem[];
    uint32_t* Ah = (uint32_t*)(smem + OFF_AH);
    uint32_t* Al = (uint32_t*)(smem + OFF_AL);
    uint32_t* Wh = (uint32_t*)(smem + OFF_WH);
    uint32_t* Wl = (uint32_t*)(smem + OFF_WL);
    float* bias_s = (float*)(smem + OFF_BIAS);

    const int tid = threadIdx.x;
    const int wid = tid >> 5;
    const int lid = tid & 31;
    const int g   = lid >> 2;
    const int tig = lid & 3;
    const int wm  = wid & 3;       // warp M index (0..3) -> rows wm*32..+32
    const int wn  = wid >> 2;      // warp N index (0..3) -> cols wn*32..+32
    const int row0 = blockIdx.x * 128;

    const uint32_t sAh = (uint32_t)__cvta_generic_to_shared(Ah);
    const uint32_t sAl = (uint32_t)__cvta_generic_to_shared(Al);
    const uint32_t sWh = (uint32_t)__cvta_generic_to_shared(Wh);
    const uint32_t sWl = (uint32_t)__cvta_generic_to_shared(Wl);

    // A fragment lane offset (16 rows x 16 cols bf16)
    const uint32_t aoff = (uint32_t)((lid & 15) * PJ_ROWB + (lid >> 4) * 16);
    // B fragment lane offset (16 n-rows x 16 k)
    const uint32_t boff = (uint32_t)(((lid & 7) + ((lid >> 4) & 1) * 8) * PJ_ROWB
                                     + ((lid >> 3) & 1) * 16);

    if (tid < 128) {
        bias_s[tid]       = u_b[tid];
        bias_s[128 + tid] = g_b[tid];
    }

    // ---- load x tile (128x128 fp32), split hi/lo bf16, store to smem ----
    {
        const float4* xp = (const float4*)(x + (size_t)row0 * DD);
        #pragma unroll
        for (int i = 0; i < 8; i++) {
            int f   = tid + i * 512;       // float4 index; 32 per row
            int row = f >> 5;
            int c4  = f & 31;
            float4 v = xp[f];
            __nv_bfloat16 h0 = __float2bfloat16_rn(v.x);
            __nv_bfloat16 h1 = __float2bfloat16_rn(v.y);
            __nv_bfloat16 h2 = __float2bfloat16_rn(v.z);
            __nv_bfloat16 h3 = __float2bfloat16_rn(v.w);
            int idx = row * PJ_STRIDE + c4 * 2;
            Ah[idx]     = pack_bf2(__bfloat162float(h0), __bfloat162float(h1));
            Ah[idx + 1] = pack_bf2(__bfloat162float(h2), __bfloat162float(h3));
            Al[idx]     = pack_bf2(v.x - __bfloat162float(h0),
                                   v.y - __bfloat162float(h1));
            Al[idx + 1] = pack_bf2(v.z - __bfloat162float(h2),
                                   v.w - __bfloat162float(h3));
        }
    }
    __syncthreads();

    for (int m = 0; m < 3; m++) {
        // ---- load weight tile m (hi/lo bf16) into smem ----
        {
            const uint4* wh = (const uint4*)(d_Wh + m * DD * DD);
            const uint4* wl = (const uint4*)(d_Wl + m * DD * DD);
            #pragma unroll
            for (int i = 0; i < 4; i++) {
                int f  = tid + i * 512;    // uint4 = 8 bf16; 16 per row
                int n  = f >> 4;
                int j4 = f & 15;
                int idx = n * PJ_STRIDE + j4 * 4;
                *(uint4*)(Wh + idx) = wh[f];
                *(uint4*)(Wl + idx) = wl[f];
            }
        }
        __syncthreads();

        float acc[2][4][4];
        #pragma unroll
        for (int i = 0; i < 2; i++)
            #pragma unroll
            for (int j = 0; j < 4; j++)
                #pragma unroll
                for (int c = 0; c < 4; c++) acc[i][j][c] = 0.0f;

        #pragma unroll
        for (int pass = 0; pass < 3; pass++) {
            const uint32_t sA = (pass == 2) ? sAl : sAh;
            const uint32_t sB = (pass == 1) ? sWl : sWh;
            #pragma unroll
            for (int ks = 0; ks < 8; ks++) {
                // A fragments: 2 x ldmatrix.x4 (rows wm*32 .. +32)
                uint32_t a[2][4];
                #pragma unroll
                for (int i = 0; i < 2; i++) {
                    uint32_t addr = sA + (uint32_t)((wm * 32 + i * 16) * PJ_ROWB
                                                    + ks * 32) + aoff;
                    ldm_x4(a[i], addr);
                }
                // B fragments: 2 x ldmatrix.x4 (cols wn*32 .. +32)
                uint32_t b[4][2];
                #pragma unroll
                for (int jp = 0; jp < 2; jp++) {
                    uint32_t r[4];
                    uint32_t addr = sB + (uint32_t)((wn * 32 + jp * 16) * PJ_ROWB
                                                    + ks * 32) + boff;
                    ldm_x4(r, addr);
                    b[2 * jp][0]     = r[0];
                    b[2 * jp][1]     = r[1];
                    b[2 * jp + 1][0] = r[2];
                    b[2 * jp + 1][1] = r[3];
                }
                #pragma unroll
                for (int i = 0; i < 2; i++)
                    #pragma unroll
                    for (int j = 0; j < 4; j++)
                        mma16816(acc[i][j], a[i], b[j]);
            }
        }

        // ---- bias + store ----
        float* dst = (m == 0) ? d_U : (m == 1) ? d_Gx : d_Ax;
        #pragma unroll
        for (int i = 0; i < 2; i++) {
            #pragma unroll
            for (int j = 0; j < 4; j++) {
                int r = row0 + wm * 32 + i * 16 + g;
                int c = wn * 32 + j * 8 + tig * 2;
                float bx = 0.0f, by = 0.0f;
                if (m < 2) {
                    bx = bias_s[m * 128 + c];
                    by = bias_s[m * 128 + c + 1];
                }
                float2 v0 = make_float2(acc[i][j][0] + bx, acc[i][j][1] + by);
                float2 v1 = make_float2(acc[i][j][2] + bx, acc[i][j][3] + by);
                *(float2*)(dst + (size_t)r * DD + c)       = v0;
                *(float2*)(dst + (size_t)(r + 8) * DD + c) = v1;
            }
        }
        __syncthreads();   // before overwriting W tile
    }
}

// ---------------------------------------------------------------------------
// Recurrent kernel (exact R5 version — best measured 1722us):
// 128 CTAs x 512 threads, o=tid>>2, q=tid&3, mb=q&1.
// ---------------------------------------------------------------------------
__global__ void __launch_bounds__(512, 1)
rwa_rec_kernel(const float* __restrict__ g_w,
               const float* __restrict__ a_w,
               const float* __restrict__ s0,
               float* __restrict__ out)
{
    __shared__ float hs[2][2][4][36];   // [buf][batch][chunk][32 + 4 pad]

    const int tid = threadIdx.x;
    const int o   = tid >> 2;
    const int q   = tid & 3;
    const int mb  = q & 1;

    ull wg[16], wa[16];
    {
        const ull* gp = (const ull*)(g_w + (size_t)o * 256 + 128 + q * 32);
        const ull* ap = (const ull*)(a_w + (size_t)o * 256 + 128 + q * 32);
        #pragma unroll
        for (int j = 0; j < 16; j++) { wg[j] = gp[j]; wa[j] = ap[j]; }
    }

    float num = 0.0f, den = 0.0f, amax = 1e-38f;
    const size_t idx0 = ((size_t)(blockIdx.x * 2 + mb)) * LSEQ * DD + o;

    if (q < 2) {
        hs[0][mb][o >> 5][o & 31] = tanhf_fast(s0[o]);
    }
    float cu = d_U[idx0], cg = d_Gx[idx0], ca = d_Ax[idx0];
    __syncthreads();

    for (int t = 0; t < LSEQ; t++) {
        float nu = 0.0f, ng = 0.0f, na = 0.0f;
        if (t + 1 < LSEQ) {
            size_t id = idx0 + (size_t)(t + 1) * DD;
            nu = d_U[id]; ng = d_Gx[id]; na = d_Ax[id];
        }

        const ulonglong2* h0p = (const ulonglong2*)&hs[t & 1][0][q][0];
        const ulonglong2* h1p = (const ulonglong2*)&hs[t & 1][1][q][0];
        ull aG0 = 0ull, aA0 = 0ull, aG1 = 0ull, aA1 = 0ull;
        #pragma unroll
        for (int j = 0; j < 8; j++) {
            ulonglong2 h0 = h0p[j];
            ulonglong2 h1 = h1p[j];
            aG0 = ffma2(wg[2*j  ], h0.x, aG0);
            aA0 = ffma2(wa[2*j  ], h0.x, aA0);
            aG1 = ffma2(wg[2*j  ], h1.x, aG1);
            aA1 = ffma2(wa[2*j  ], h1.x, aA1);
            aG0 = ffma2(wg[2*j+1], h0.y, aG0);
            aA0 = ffma2(wa[2*j+1], h0.y, aA0);
            aG1 = ffma2(wg[2*j+1], h1.y, aG1);
            aA1 = ffma2(wa[2*j+1], h1.y, aA1);
        }
        float2 s;
        s = upk2(aG0); float sG0 = s.x + s.y;
        s = upk2(aA0); float sA0 = s.x + s.y;
        s = upk2(aG1); float sG1 = s.x + s.y;
        s = upk2(aA1); float sA1 = s.x + s.y;

        float sendG = mb ? sG0 : sG1;
        float sendA = mb ? sA0 : sA1;
        float rG = __shfl_xor_sync(0xffffffffu, sendG, 1);
        float rA = __shfl_xor_sync(0xffffffffu, sendA, 1);
        float myG = (mb ? sG1 : sG0) + rG;
        float myA = (mb ? sA1 : sA0) + rA;
        myG += __shfl_xor_sync(0xffffffffu, myG, 2);
        myA += __shfl_xor_sync(0xffffffffu, myA, 2);

        float g  = tanh_hw(cg + myG);
        float z  = cu * g;
        float a  = ca + myA;
        float m  = fmaxf(a, amax);
        float e  = __expf(m - amax);
        amax = m;
        num  = fmaf(z, e, num);
        den += e;
        float h = tanh_hw(__fdividef(num, den));

        if (q < 2) {
            hs[(t + 1) & 1][mb][o >> 5][o & 31] = h;
            out[idx0 + (size_t)t * DD] = h;
        }

        cu = nu; cg = ng; ca = na;
        __syncthreads();
    }
}

// ---------------------------------------------------------------------------
// kernel_launch
// Input order (metadata): 0:x  1:s0  2:u_w  3:u_b  4:g_w  5:g_b  6:a_w
// ---------------------------------------------------------------------------
extern "C" void kernel_launch(void* const* d_in, const int* in_sizes, int n_in,
                              void* d_out, int out_size)
{
    const float* x   = (const float*)d_in[0];
    const float* s0  = (const float*)d_in[1];
    const float* u_w = (const float*)d_in[2];
    const float* u_b = (const float*)d_in[3];
    const float* g_w = (const float*)d_in[4];
    const float* g_b = (const float*)d_in[5];
    const float* a_w = (const float*)d_in[6];
    float* out = (float*)d_out;

    // 1) split weights to bf16 hi/lo
    rwa_prep_kernel<<<(3 * DD * DD + 255) / 256, 256>>>(u_w, g_w, a_w);

    // 2) projections on tensor cores (mma.sync bf16, 16 warps)
    cudaFuncSetAttribute(rwa_proj_mma_kernel,
                         cudaFuncAttributeMaxDynamicSharedMemorySize, PJ_SMEM);
    rwa_proj_mma_kernel<<<(BSZ * LSEQ) / 128, 512, PJ_SMEM>>>(x, u_b, g_b);

    // 3) recurrence (proven R5 config)
    rwa_rec_kernel<<<BSZ / 2, 512>>>(g_w, a_w, s0, out);
}

// round 17
// speedup vs baseline: 2.0573x; 1.1052x over previous
#include <cuda_runtime.h>
#include <cuda_bf16.h>
#include <cuda_fp16.h>
#include <cstdint>

typedef unsigned long long ull;

#define BSZ   256
#define LSEQ  2048
#define DD    128   // DIN == DOUT == 128

// ---------------------------------------------------------------------------
// Scratch: projections (fp32) + pre-split fp16 weights (hi/lo).
// ---------------------------------------------------------------------------
__device__ float d_U [BSZ * LSEQ * DD];
__device__ float d_Gx[BSZ * LSEQ * DD];
__device__ float d_Ax[BSZ * LSEQ * DD];
__device__ __half d_Wh[3 * DD * DD];   // [m][o][d] K-major, fp16 hi
__device__ __half d_Wl[3 * DD * DD];   // fp16 residual (W to ~2^-22)

// ---------------------------------------------------------------------------
// small helpers
// ---------------------------------------------------------------------------
__device__ __forceinline__ ull ffma2(ull a, ull b, ull c) {
    ull d;
    asm("fma.rn.f32x2 %0, %1, %2, %3;" : "=l"(d) : "l"(a), "l"(b), "l"(c));
    return d;
}
__device__ __forceinline__ float2 upk2(ull v) {
    float2 f;
    asm("mov.b64 {%0, %1}, %2;" : "=f"(f.x), "=f"(f.y) : "l"(v));
    return f;
}
__device__ __forceinline__ float tanh_hw(float x) {
    float r;
    asm("tanh.approx.f32 %0, %1;" : "=f"(r) : "f"(x));
    return r;
}
__device__ __forceinline__ float tanhf_fast(float x) {
    float ax = fabsf(x);
    float e  = __expf(-2.0f * ax);
    float r  = __fdividef(1.0f - e, 1.0f + e);
    return copysignf(r, x);
}
__device__ __forceinline__ uint32_t pack_h2(float a, float b) {
    __half2 t = __floats2half2_rn(a, b);
    return *(uint32_t*)&t;
}

// mma.sync m16n8k16 row.col f32.f16.f16.f32 (baseline PTX, legal at compute_103)
__device__ __forceinline__ void mma16816(float* c, const uint32_t* a, const uint32_t* b) {
    asm volatile(
        "mma.sync.aligned.m16n8k16.row.col.f32.f16.f16.f32 "
        "{%0,%1,%2,%3}, {%4,%5,%6,%7}, {%8,%9}, {%0,%1,%2,%3};"
        : "+f"(c[0]), "+f"(c[1]), "+f"(c[2]), "+f"(c[3])
        : "r"(a[0]), "r"(a[1]), "r"(a[2]), "r"(a[3]), "r"(b[0]), "r"(b[1]));
}

// ldmatrix x4 (baseline PTX sm_75+)
__device__ __forceinline__ void ldm_x4(uint32_t* r, uint32_t saddr) {
    asm volatile("ldmatrix.sync.aligned.m8n8.x4.shared.b16 {%0,%1,%2,%3}, [%4];"
                 : "=r"(r[0]), "=r"(r[1]), "=r"(r[2]), "=r"(r[3]) : "r"(saddr));
}

// ---------------------------------------------------------------------------
// Prep kernel: split weights into fp16 hi/lo (once, tiny).
//   m=0: u_w (pitch 128); m=1: g_w[:, :128] (pitch 256); m=2: a_w[:, :128]
// ---------------------------------------------------------------------------
__global__ void rwa_prep_kernel(const float* __restrict__ u_w,
                                const float* __restrict__ g_w,
                                const float* __restrict__ a_w)
{
    int idx = blockIdx.x * blockDim.x + threadIdx.x;
    if (idx >= 3 * DD * DD) return;
    int m = idx / (DD * DD);
    int r = idx - m * DD * DD;
    int o = r >> 7, d = r & 127;
    float w = (m == 0) ? u_w[o * 128 + d]
            : (m == 1) ? g_w[o * 256 + d]
                       : a_w[o * 256 + d];
    __half h = __float2half_rn(w);
    float res = w - __half2float(h);
    d_Wh[idx] = h;
    d_Wl[idx] = __float2half_rn(res);
}

// ---------------------------------------------------------------------------
// Projection GEMM on tensor cores, 2-pass fp16 split:
//   D = A * Whi + A * Wlo,  A = fp16(x) (unsplit), fp32 accumulators.
// Error: dropped term is (x - fp16(x))*W ~ 2^-12 relative — ~5-10x under gate.
// Per CTA: M=128 rows x K=128, three N=128 outputs (U, Gx, Ax).
// 8 warps = 4(M) x 2(N); warp tile 32x64 = 2 x 8 m16n8k16 tiles (the proven
// 256-thread shape — 512 threads measured slower). ldmatrix fragments.
// ---------------------------------------------------------------------------
#define PJ_STRIDE 68                       // b32 words per smem row
#define PJ_ROWB   (PJ_STRIDE * 4)          // 272 bytes
#define OFF_A  0
#define OFF_WH (OFF_A  + 128 * PJ_ROWB)    // 34816
#define OFF_WL (OFF_WH + 128 * PJ_ROWB)    // 69632
#define OFF_BIAS (OFF_WL + 128 * PJ_ROWB)  // 104448
#define PJ_SMEM (OFF_BIAS + 1024)          // 105472

__global__ void __launch_bounds__(256, 1)
rwa_proj_mma_kernel(const float* __restrict__ x,
                    const float* __restrict__ u_b,
                    const float* __restrict__ g_b)
{
    extern __shared__ char smem[];
    uint32_t* As = (uint32_t*)(smem + OFF_A);
    uint32_t* Wh = (uint32_t*)(smem + OFF_WH);
    uint32_t* Wl = (uint32_t*)(smem + OFF_WL);
    float* bias_s = (float*)(smem + OFF_BIAS);

    const int tid = threadIdx.x;
    const int wid = tid >> 5;
    const int lid = tid & 31;
    const int g   = lid >> 2;
    const int tig = lid & 3;
    const int wm  = wid & 3;       // warp M index (0..3) -> rows wm*32..+32
    const int wn  = wid >> 2;      // warp N index (0..1) -> cols wn*64..+64
    const int row0 = blockIdx.x * 128;

    const uint32_t sA  = (uint32_t)__cvta_generic_to_shared(As);
    const uint32_t sWh = (uint32_t)__cvta_generic_to_shared(Wh);
    const uint32_t sWl = (uint32_t)__cvta_generic_to_shared(Wl);

    // A fragment lane offset (16 rows x 16 cols fp16)
    const uint32_t aoff = (uint32_t)((lid & 15) * PJ_ROWB + (lid >> 4) * 16);
    // B fragment lane offset (16 n-rows x 16 k)
    const uint32_t boff = (uint32_t)(((lid & 7) + ((lid >> 4) & 1) * 8) * PJ_ROWB
                                     + ((lid >> 3) & 1) * 16);

    if (tid < 128) {
        bias_s[tid]       = u_b[tid];
        bias_s[128 + tid] = g_b[tid];
    }

    // ---- load x tile (128x128 fp32), convert fp16, store to smem ----
    {
        const float4* xp = (const float4*)(x + (size_t)row0 * DD);
        #pragma unroll
        for (int i = 0; i < 16; i++) {
            int f   = tid + i * 256;       // float4 index; 32 per row
            int row = f >> 5;
            int c4  = f & 31;
            float4 v = xp[f];
            int idx = row * PJ_STRIDE + c4 * 2;
            As[idx]     = pack_h2(v.x, v.y);
            As[idx + 1] = pack_h2(v.z, v.w);
        }
    }
    __syncthreads();

    for (int m = 0; m < 3; m++) {
        // ---- load weight tile m (hi/lo fp16) into smem ----
        {
            const uint4* wh = (const uint4*)(d_Wh + m * DD * DD);
            const uint4* wl = (const uint4*)(d_Wl + m * DD * DD);
            #pragma unroll
            for (int i = 0; i < 8; i++) {
                int f  = tid + i * 256;    // uint4 = 8 fp16; 16 per row
                int n  = f >> 4;
                int j4 = f & 15;
                int idx = n * PJ_STRIDE + j4 * 4;
                *(uint4*)(Wh + idx) = wh[f];
                *(uint4*)(Wl + idx) = wl[f];
            }
        }
        __syncthreads();

        float acc[2][8][4];
        #pragma unroll
        for (int i = 0; i < 2; i++)
            #pragma unroll
            for (int j = 0; j < 8; j++)
                #pragma unroll
                for (int c = 0; c < 4; c++) acc[i][j][c] = 0.0f;

        #pragma unroll
        for (int pass = 0; pass < 2; pass++) {
            const uint32_t sB = (pass == 1) ? sWl : sWh;
            #pragma unroll
            for (int ks = 0; ks < 8; ks++) {
                // A fragments: 2 x ldmatrix.x4
                uint32_t a[2][4];
                #pragma unroll
                for (int i = 0; i < 2; i++) {
                    uint32_t addr = sA + (uint32_t)((wm * 32 + i * 16) * PJ_ROWB
                                                    + ks * 32) + aoff;
                    ldm_x4(a[i], addr);
                }
                // B fragments: 4 x ldmatrix.x4 (each covers 2 n-tiles)
                uint32_t b[8][2];
                #pragma unroll
                for (int jp = 0; jp < 4; jp++) {
                    uint32_t r[4];
                    uint32_t addr = sB + (uint32_t)((wn * 64 + jp * 16) * PJ_ROWB
                                                    + ks * 32) + boff;
                    ldm_x4(r, addr);
                    b[2 * jp][0]     = r[0];
                    b[2 * jp][1]     = r[1];
                    b[2 * jp + 1][0] = r[2];
                    b[2 * jp + 1][1] = r[3];
                }
                #pragma unroll
                for (int i = 0; i < 2; i++)
                    #pragma unroll
                    for (int j = 0; j < 8; j++)
                        mma16816(acc[i][j], a[i], b[j]);
            }
        }

        // ---- bias + store ----
        float* dst = (m == 0) ? d_U : (m == 1) ? d_Gx : d_Ax;
        #pragma unroll
        for (int i = 0; i < 2; i++) {
            #pragma unroll
            for (int j = 0; j < 8; j++) {
                int r = row0 + wm * 32 + i * 16 + g;
                int c = wn * 64 + j * 8 + tig * 2;
                float bx = 0.0f, by = 0.0f;
                if (m < 2) {
                    bx = bias_s[m * 128 + c];
                    by = bias_s[m * 128 + c + 1];
                }
                float2 v0 = make_float2(acc[i][j][0] + bx, acc[i][j][1] + by);
                float2 v1 = make_float2(acc[i][j][2] + bx, acc[i][j][3] + by);
                *(float2*)(dst + (size_t)r * DD + c)       = v0;
                *(float2*)(dst + (size_t)(r + 8) * DD + c) = v1;
            }
        }
        __syncthreads();   // before overwriting W tile
    }
}

// ---------------------------------------------------------------------------
// Recurrent kernel (exact R5 version — best measured 1722us):
// 128 CTAs x 512 threads, o=tid>>2, q=tid&3, mb=q&1.
// ---------------------------------------------------------------------------
__global__ void __launch_bounds__(512, 1)
rwa_rec_kernel(const float* __restrict__ g_w,
               const float* __restrict__ a_w,
               const float* __restrict__ s0,
               float* __restrict__ out)
{
    __shared__ float hs[2][2][4][36];   // [buf][batch][chunk][32 + 4 pad]

    const int tid = threadIdx.x;
    const int o   = tid >> 2;
    const int q   = tid & 3;
    const int mb  = q & 1;

    ull wg[16], wa[16];
    {
        const ull* gp = (const ull*)(g_w + (size_t)o * 256 + 128 + q * 32);
        const ull* ap = (const ull*)(a_w + (size_t)o * 256 + 128 + q * 32);
        #pragma unroll
        for (int j = 0; j < 16; j++) { wg[j] = gp[j]; wa[j] = ap[j]; }
    }

    float num = 0.0f, den = 0.0f, amax = 1e-38f;
    const size_t idx0 = ((size_t)(blockIdx.x * 2 + mb)) * LSEQ * DD + o;

    if (q < 2) {
        hs[0][mb][o >> 5][o & 31] = tanhf_fast(s0[o]);
    }
    float cu = d_U[idx0], cg = d_Gx[idx0], ca = d_Ax[idx0];
    __syncthreads();

    for (int t = 0; t < LSEQ; t++) {
        float nu = 0.0f, ng = 0.0f, na = 0.0f;
        if (t + 1 < LSEQ) {
            size_t id = idx0 + (size_t)(t + 1) * DD;
            nu = d_U[id]; ng = d_Gx[id]; na = d_Ax[id];
        }

        const ulonglong2* h0p = (const ulonglong2*)&hs[t & 1][0][q][0];
        const ulonglong2* h1p = (const ulonglong2*)&hs[t & 1][1][q][0];
        ull aG0 = 0ull, aA0 = 0ull, aG1 = 0ull, aA1 = 0ull;
        #pragma unroll
        for (int j = 0; j < 8; j++) {
            ulonglong2 h0 = h0p[j];
            ulonglong2 h1 = h1p[j];
            aG0 = ffma2(wg[2*j  ], h0.x, aG0);
            aA0 = ffma2(wa[2*j  ], h0.x, aA0);
            aG1 = ffma2(wg[2*j  ], h1.x, aG1);
            aA1 = ffma2(wa[2*j  ], h1.x, aA1);
            aG0 = ffma2(wg[2*j+1], h0.y, aG0);
            aA0 = ffma2(wa[2*j+1], h0.y, aA0);
            aG1 = ffma2(wg[2*j+1], h1.y, aG1);
            aA1 = ffma2(wa[2*j+1], h1.y, aA1);
        }
        float2 s;
        s = upk2(aG0); float sG0 = s.x + s.y;
        s = upk2(aA0); float sA0 = s.x + s.y;
        s = upk2(aG1); float sG1 = s.x + s.y;
        s = upk2(aA1); float sA1 = s.x + s.y;

        float sendG = mb ? sG0 : sG1;
        float sendA = mb ? sA0 : sA1;
        float rG = __shfl_xor_sync(0xffffffffu, sendG, 1);
        float rA = __shfl_xor_sync(0xffffffffu, sendA, 1);
        float myG = (mb ? sG1 : sG0) + rG;
        float myA = (mb ? sA1 : sA0) + rA;
        myG += __shfl_xor_sync(0xffffffffu, myG, 2);
        myA += __shfl_xor_sync(0xffffffffu, myA, 2);

        float g  = tanh_hw(cg + myG);
        float z  = cu * g;
        float a  = ca + myA;
        float m  = fmaxf(a, amax);
        float e  = __expf(m - amax);
        amax = m;
        num  = fmaf(z, e, num);
        den += e;
        float h = tanh_hw(__fdividef(num, den));

        if (q < 2) {
            hs[(t + 1) & 1][mb][o >> 5][o & 31] = h;
            out[idx0 + (size_t)t * DD] = h;
        }

        cu = nu; cg = ng; ca = na;
        __syncthreads();
    }
}

// ---------------------------------------------------------------------------
// kernel_launch
// Input order (metadata): 0:x  1:s0  2:u_w  3:u_b  4:g_w  5:g_b  6:a_w
// ---------------------------------------------------------------------------
extern "C" void kernel_launch(void* const* d_in, const int* in_sizes, int n_in,
                              void* d_out, int out_size)
{
    const float* x   = (const float*)d_in[0];
    const float* s0  = (const float*)d_in[1];
    const float* u_w = (const float*)d_in[2];
    const float* u_b = (const float*)d_in[3];
    const float* g_w = (const float*)d_in[4];
    const float* g_b = (const float*)d_in[5];
    const float* a_w = (const float*)d_in[6];
    float* out = (float*)d_out;

    // 1) split weights to fp16 hi/lo
    rwa_prep_kernel<<<(3 * DD * DD + 255) / 256, 256>>>(u_w, g_w, a_w);

    // 2) projections on tensor cores (mma.sync fp16, 2-pass split)
    cudaFuncSetAttribute(rwa_proj_mma_kernel,
                         cudaFuncAttributeMaxDynamicSharedMemorySize, PJ_SMEM);
    rwa_proj_mma_kernel<<<(BSZ * LSEQ) / 128, 256, PJ_SMEM>>>(x, u_b, g_b);

    // 3) recurrence (proven R5 config)
    rwa_rec_kernel<<<BSZ / 2, 512>>>(g_w, a_w, s0, out);
}